// round 4
// baseline (speedup 1.0000x reference)
#include <cuda_runtime.h>
#include <cuda_bf16.h>

// Problem constants
#define TT    256
#define BB    1000
#define DD    300
#define H4    8
#define NCONS_BLK 16            // consumer blocks (last 16 of grid)
#define DCH   20                // d-cols per chunk (80B per row)
#define NCH   15                // 15 * 20 = 300
#define CHUNK_OPS (BB * 5)      // 5000 x 16B cp.async per chunk
#define SXF   (BB * DCH)        // 20000 floats per buffer

// smem (floats): sW[2400] | sB[8] | pad->2416 | sx0[20000] | sx1[20000]
#define SW_FLOATS 2400
#define SX_OFF    2416
#define SMEM_FLOATS (SX_OFF + 2 * SXF)
#define SMEM_BYTES  (SMEM_FLOATS * 4)    // 169,664 B

__device__ float g_xg[TT * BB * H4];   // xg[t][b][g]  (8.192 MB)
__device__ int   g_flags[TT];

// ---------------- PTX helpers ----------------
#define CP_ASYNC16(dst_u32, src_ptr) \
    asm volatile("cp.async.cg.shared.global [%0], [%1], 16;" :: "r"(dst_u32), "l"(src_ptr))
#define CP_COMMIT()  asm volatile("cp.async.commit_group;")
#define CP_WAIT1()   asm volatile("cp.async.wait_group 1;")
#define CP_WAIT0()   asm volatile("cp.async.wait_group 0;")

__device__ __forceinline__ void fma2(unsigned long long& acc,
                                     unsigned long long a,
                                     unsigned long long b) {
    asm volatile("fma.rn.f32x2 %0, %1, %2, %3;" : "=l"(acc) : "l"(a), "l"(b), "l"(acc));
}
__device__ __forceinline__ unsigned long long pack2(float x) {
    unsigned long long r;
    asm("mov.b64 %0, {%1, %1};" : "=l"(r) : "r"(__float_as_uint(x)));
    return r;
}
__device__ __forceinline__ void unpack2(unsigned long long p, float& lo, float& hi) {
    unsigned a, b;
    asm("mov.b64 {%0, %1}, %2;" : "=r"(a), "=r"(b) : "l"(p));
    lo = __uint_as_float(a);
    hi = __uint_as_float(b);
}

__device__ __forceinline__ void set_flag(int t) {
    asm volatile("st.release.gpu.global.u32 [%0], %1;" :: "l"(&g_flags[t]), "r"(1u) : "memory");
}
__device__ __forceinline__ void wait_flag(int t) {
    unsigned v;
    for (;;) {
        asm volatile("ld.acquire.gpu.global.u32 %0, [%1];"
                     : "=r"(v) : "l"(&g_flags[t]) : "memory");
        if (v) return;
        __nanosleep(32);
    }
}

// fast overflow-safe activations (~1e-6 accurate)
__device__ __forceinline__ float sigf(float x) {
    x = fminf(fmaxf(x, -30.0f), 30.0f);
    return __fdividef(1.0f, 1.0f + __expf(-x));
}
__device__ __forceinline__ float tanh_(float x) {
    x = fminf(fmaxf(x, -15.0f), 15.0f);
    float e = __expf(-2.0f * x);
    return __fdividef(1.0f - e, 1.0f + e);
}

__global__ void reset_kernel() {
    g_flags[threadIdx.x] = 0;
}

// stage chunk (t, c) into buffer `par` — i-contiguous 16B ops for coalescing
__device__ __forceinline__ void stage_chunk(const float* __restrict__ x,
                                            int t, int c,
                                            unsigned ubase, int par, int tid) {
    const char* src = reinterpret_cast<const char*>(x)
                    + (size_t)t * (BB * DD * 4) + c * (DCH * 4);
    unsigned dst = ubase + (unsigned)par * (SXF * 4);
    #pragma unroll 1
    for (int i = tid; i < CHUNK_OPS; i += 256) {
        int r = i / 5;
        int q = i - r * 5;
        CP_ASYNC16(dst + r * (DCH * 4) + q * 16, src + (size_t)r * (DD * 4) + q * 16);
    }
    CP_COMMIT();
}

__global__ __launch_bounds__(256) void fused_kernel(
    const float* __restrict__ x,      // [T,B,300]
    const float* __restrict__ Wih0,   // [8,300]
    const float* __restrict__ bih0,
    const float* __restrict__ bhh0,
    const float* __restrict__ h0in,   // [2,B,2]
    const float* __restrict__ c0in,
    const float* __restrict__ Whh0,   // [8,2]
    const float* __restrict__ Wih1,   // [8,2]
    const float* __restrict__ Whh1,   // [8,2]
    const float* __restrict__ bih1,
    const float* __restrict__ bhh1,
    const float* __restrict__ Wlin,   // [1,2]
    const float* __restrict__ blin,
    float* __restrict__ out,          // [B]
    int nprod)
{
    extern __shared__ float smem[];
    const int bid = blockIdx.x;
    const int tid = threadIdx.x;

    if (bid < nprod) {
        // =================== PRODUCER ===================
        float* sW = smem;                  // sW[d*8+g] = Wih0[g*300+d]
        float* sB = smem + SW_FLOATS;
        unsigned ubase = (unsigned)__cvta_generic_to_shared(smem + SX_OFF);

        for (int i = tid; i < DD * H4; i += 256) {
            int d = i >> 3, g = i & 7;
            sW[i] = Wih0[g * DD + d];
        }
        if (tid < H4) sB[tid] = bih0[tid] + bhh0[tid];
        __syncthreads();

        ulonglong2 bias01 = *reinterpret_cast<const ulonglong2*>(&sB[0]);
        ulonglong2 bias23 = *reinterpret_cast<const ulonglong2*>(&sB[4]);
        const ulonglong2* wpb = reinterpret_cast<const ulonglong2*>(sW);

        int spar = 0;   // parity for next staged chunk
        int cpar = 0;   // parity for next computed chunk

        if (bid < TT) {
            // prologue: stage chunks 0,1 of first task
            stage_chunk(x, bid, 0, ubase, spar, tid); spar ^= 1;
            stage_chunk(x, bid, 1, ubase, spar, tid); spar ^= 1;

            #pragma unroll 1
            for (int t = bid; t < TT; t += nprod) {
                const int tn = t + nprod;             // next task (may be >= TT)
                const bool last_task = (tn >= TT);

                unsigned long long acc[4][4];
                #pragma unroll
                for (int k = 0; k < 4; k++) {
                    acc[k][0] = bias01.x; acc[k][1] = bias01.y;
                    acc[k][2] = bias23.x; acc[k][3] = bias23.y;
                }

                #pragma unroll 1
                for (int c = 0; c < NCH; c++) {
                    if (last_task && c == NCH - 1) { CP_WAIT0(); }
                    else                           { CP_WAIT1(); }
                    __syncthreads();

                    // ---- compute chunk c from buffer cpar ----
                    if (tid < 250) {
                        const float* sx = smem + SX_OFF + cpar * SXF;
                        const float4* xr0 = reinterpret_cast<const float4*>(sx + (tid      ) * DCH);
                        const float4* xr1 = reinterpret_cast<const float4*>(sx + (tid + 250) * DCH);
                        const float4* xr2 = reinterpret_cast<const float4*>(sx + (tid + 500) * DCH);
                        const float4* xr3 = reinterpret_cast<const float4*>(sx + (tid + 750) * DCH);
                        const ulonglong2* wp = wpb + c * (DCH * 2);
                        #pragma unroll
                        for (int dq = 0; dq < DCH / 4; dq++) {
                            float4 xv[4];
                            xv[0] = xr0[dq]; xv[1] = xr1[dq];
                            xv[2] = xr2[dq]; xv[3] = xr3[dq];
                            #pragma unroll
                            for (int j = 0; j < 4; j++) {
                                ulonglong2 wA = wp[(dq * 4 + j) * 2];
                                ulonglong2 wB = wp[(dq * 4 + j) * 2 + 1];
                                const float xs0 = (j == 0) ? xv[0].x : (j == 1) ? xv[0].y : (j == 2) ? xv[0].z : xv[0].w;
                                const float xs1 = (j == 0) ? xv[1].x : (j == 1) ? xv[1].y : (j == 2) ? xv[1].z : xv[1].w;
                                const float xs2 = (j == 0) ? xv[2].x : (j == 1) ? xv[2].y : (j == 2) ? xv[2].z : xv[2].w;
                                const float xs3 = (j == 0) ? xv[3].x : (j == 1) ? xv[3].y : (j == 2) ? xv[3].z : xv[3].w;
                                unsigned long long p0 = pack2(xs0), p1 = pack2(xs1);
                                unsigned long long p2 = pack2(xs2), p3 = pack2(xs3);
                                fma2(acc[0][0], p0, wA.x); fma2(acc[0][1], p0, wA.y);
                                fma2(acc[0][2], p0, wB.x); fma2(acc[0][3], p0, wB.y);
                                fma2(acc[1][0], p1, wA.x); fma2(acc[1][1], p1, wA.y);
                                fma2(acc[1][2], p1, wB.x); fma2(acc[1][3], p1, wB.y);
                                fma2(acc[2][0], p2, wA.x); fma2(acc[2][1], p2, wA.y);
                                fma2(acc[2][2], p2, wB.x); fma2(acc[2][3], p2, wB.y);
                                fma2(acc[3][0], p3, wA.x); fma2(acc[3][1], p3, wA.y);
                                fma2(acc[3][2], p3, wB.x); fma2(acc[3][3], p3, wB.y);
                            }
                        }
                    }
                    cpar ^= 1;
                    __syncthreads();   // everyone done reading buffer before restaging it

                    // ---- stage chunk (current + 2), possibly of next task ----
                    if (c < NCH - 2) {
                        stage_chunk(x, t, c + 2, ubase, spar, tid); spar ^= 1;
                    } else if (!last_task) {
                        stage_chunk(x, tn, c + 2 - NCH, ubase, spar, tid); spar ^= 1;
                    }
                }

                // ---- writeback + publish ----
                if (tid < 250) {
                    #pragma unroll
                    for (int k = 0; k < 4; k++) {
                        const int row = t * BB + tid + k * 250;
                        float4 o0, o1;
                        unpack2(acc[k][0], o0.x, o0.y);
                        unpack2(acc[k][1], o0.z, o0.w);
                        unpack2(acc[k][2], o1.x, o1.y);
                        unpack2(acc[k][3], o1.z, o1.w);
                        float4* dst = reinterpret_cast<float4*>(&g_xg[(size_t)row * H4]);
                        dst[0] = o0;
                        dst[1] = o1;
                    }
                }
                __threadfence();
                __syncthreads();
                if (tid == 0) set_flag(t);
            }
        }
        return;
    }

    // =================== CONSUMER ===================
    // 16 blocks x 4 warps (threads 0..127). Lanes 0-15: layer0 of 16 elements,
    // lanes 16-31: layer1 of the same elements, lagged one timestep.
    if (tid >= 128) return;
    const int warp = tid >> 5;
    const int lane = tid & 31;
    const bool l1  = (lane >= 16);
    const int e    = ((bid - nprod) * 4 + warp) * 16 + (lane & 15);
    const int b    = (e < BB) ? e : (BB - 1);

    float A0[H4], A1[H4], C0[H4], C1[H4], vb[H4];
    float ha, hb, ca, cb;
    float hpa = 0.0f, hpb = 0.0f;

    if (!l1) {
        #pragma unroll
        for (int g = 0; g < H4; g++) {
            A0[g] = __ldg(&Whh0[g * 2 + 0]);
            A1[g] = __ldg(&Whh0[g * 2 + 1]);
            C0[g] = 0.0f; C1[g] = 0.0f; vb[g] = 0.0f;
        }
        ha = h0in[b * 2 + 0]; hb = h0in[b * 2 + 1];
        ca = c0in[b * 2 + 0]; cb = c0in[b * 2 + 1];
    } else {
        #pragma unroll
        for (int g = 0; g < H4; g++) {
            A0[g] = __ldg(&Whh1[g * 2 + 0]);
            A1[g] = __ldg(&Whh1[g * 2 + 1]);
            C0[g] = __ldg(&Wih1[g * 2 + 0]);
            C1[g] = __ldg(&Wih1[g * 2 + 1]);
            vb[g] = __ldg(&bih1[g]) + __ldg(&bhh1[g]);
        }
        ha = h0in[BB * 2 + b * 2 + 0]; hb = h0in[BB * 2 + b * 2 + 1];
        ca = c0in[BB * 2 + b * 2 + 0]; cb = c0in[BB * 2 + b * 2 + 1];
    }
    const float wl0 = __ldg(&Wlin[0]), wl1 = __ldg(&Wlin[1]), bl = __ldg(&blin[0]);

    const float4* xg4 = reinterpret_cast<const float4*>(g_xg);
    const int idx0 = b * 2;

    wait_flag(0);
    if (!l1) {
        float4 v0 = xg4[idx0];
        float4 v1 = xg4[idx0 + 1];
        vb[0] = v0.x; vb[1] = v0.y; vb[2] = v0.z; vb[3] = v0.w;
        vb[4] = v1.x; vb[5] = v1.y; vb[6] = v1.z; vb[7] = v1.w;
    }

    for (int s = 0; s <= TT; s++) {
        float4 n0, n1;
        const bool pf = (s + 1 < TT);
        if (pf) {
            wait_flag(s + 1);
            if (!l1) {
                n0 = xg4[idx0 + (s + 1) * (BB * 2)];
                n1 = xg4[idx0 + (s + 1) * (BB * 2) + 1];
            }
        }

        float pre[H4];
        #pragma unroll
        for (int g = 0; g < H4; g++)
            pre[g] = fmaf(C0[g], hpa, fmaf(C1[g], hpb, vb[g]));
        #pragma unroll
        for (int g = 0; g < H4; g++)
            pre[g] = fmaf(A0[g], ha, fmaf(A1[g], hb, pre[g]));

        float i0 = sigf(pre[0]),  i1 = sigf(pre[1]);
        float f0 = sigf(pre[2]),  f1 = sigf(pre[3]);
        float g0 = tanh_(pre[4]), g1 = tanh_(pre[5]);
        float o0 = sigf(pre[6]),  o1 = sigf(pre[7]);
        float nca = fmaf(f0, ca, i0 * g0);
        float ncb = fmaf(f1, cb, i1 * g1);
        float nha = o0 * tanh_(nca);
        float nhb = o1 * tanh_(ncb);

        const bool valid = l1 ? (s >= 1) : (s < TT);
        if (valid) { ca = nca; cb = ncb; ha = nha; hb = nhb; }

        hpa = __shfl_up_sync(0xffffffffu, ha, 16);
        hpb = __shfl_up_sync(0xffffffffu, hb, 16);

        if (pf && !l1) {
            vb[0] = n0.x; vb[1] = n0.y; vb[2] = n0.z; vb[3] = n0.w;
            vb[4] = n1.x; vb[5] = n1.y; vb[6] = n1.z; vb[7] = n1.w;
        }
    }

    if (l1 && e < BB)
        out[b] = fmaf(wl0, ha, fmaf(wl1, hb, bl));
}

// ---------------------------------------------------------------------------
extern "C" void kernel_launch(void* const* d_in, const int* in_sizes, int n_in,
                              void* d_out, int out_size)
{
    const float* x     = (const float*)d_in[0];
    const float* h0    = (const float*)d_in[1];
    const float* c0    = (const float*)d_in[2];
    const float* Wih0  = (const float*)d_in[3];
    const float* Whh0  = (const float*)d_in[4];
    const float* bih0  = (const float*)d_in[5];
    const float* bhh0  = (const float*)d_in[6];
    const float* Wih1  = (const float*)d_in[7];
    const float* Whh1  = (const float*)d_in[8];
    const float* bih1  = (const float*)d_in[9];
    const float* bhh1  = (const float*)d_in[10];
    const float* Wlin  = (const float*)d_in[11];
    const float* blin  = (const float*)d_in[12];
    float* out = (float*)d_out;

    int dev = 0, nsm = 148;
    cudaGetDevice(&dev);
    cudaDeviceGetAttribute(&nsm, cudaDevAttrMultiProcessorCount, dev);
    if (nsm < NCONS_BLK + 8) nsm = NCONS_BLK + 8;
    int nprod = nsm - NCONS_BLK;

    cudaFuncSetAttribute(fused_kernel, cudaFuncAttributeMaxDynamicSharedMemorySize, SMEM_BYTES);

    reset_kernel<<<1, TT>>>();
    fused_kernel<<<nsm, 256, SMEM_BYTES>>>(
        x, Wih0, bih0, bhh0,
        h0, c0, Whh0, Wih1, Whh1, bih1, bhh1, Wlin, blin,
        out, nprod);
}

// round 5
// speedup vs baseline: 1.2180x; 1.2180x over previous
#include <cuda_runtime.h>
#include <cuda_bf16.h>

// Problem constants
#define TT    256
#define BB    1000
#define DD    300
#define H4    8
#define NCONS_BLK 16            // consumer blocks (last 16 of grid)
#define DCH   20                // d-cols per chunk
#define NCH   15                // 15 * 20 = 300
#define NSTG  20                // float4 ops per staging thread (250 threads * 20 = 5000)
#define SXF   (BB * DCH)        // 20000 floats per buffer (single buffer)

// smem (floats): sW[2400] | sB[8] | pad->2416 | sx[20000]
#define SW_FLOATS 2400
#define SX_OFF    2416
#define SMEM_FLOATS (SX_OFF + SXF)
#define SMEM_BYTES  (SMEM_FLOATS * 4)    // 89,664 B

__device__ float g_xg[TT * BB * H4];   // xg[t][b][g]  (8.192 MB)
__device__ int   g_flags[TT];

// ---------------- helpers ----------------
__device__ __forceinline__ void fma2(unsigned long long& acc,
                                     unsigned long long a,
                                     unsigned long long b) {
    asm volatile("fma.rn.f32x2 %0, %1, %2, %3;" : "=l"(acc) : "l"(a), "l"(b), "l"(acc));
}
__device__ __forceinline__ unsigned long long pack2(float x) {
    unsigned long long r;
    asm("mov.b64 %0, {%1, %1};" : "=l"(r) : "r"(__float_as_uint(x)));
    return r;
}
__device__ __forceinline__ void unpack2(unsigned long long p, float& lo, float& hi) {
    unsigned a, b;
    asm("mov.b64 {%0, %1}, %2;" : "=r"(a), "=r"(b) : "l"(p));
    lo = __uint_as_float(a);
    hi = __uint_as_float(b);
}

__device__ __forceinline__ void set_flag(int t) {
    asm volatile("st.release.gpu.global.u32 [%0], %1;" :: "l"(&g_flags[t]), "r"(1u) : "memory");
}
__device__ __forceinline__ void wait_flag(int t) {
    unsigned v;
    for (;;) {
        asm volatile("ld.acquire.gpu.global.u32 %0, [%1];"
                     : "=r"(v) : "l"(&g_flags[t]) : "memory");
        if (v) return;
        __nanosleep(32);
    }
}

// fast overflow-safe activations (~1e-6 accurate)
__device__ __forceinline__ float sigf(float x) {
    x = fminf(fmaxf(x, -30.0f), 30.0f);
    return __fdividef(1.0f, 1.0f + __expf(-x));
}
__device__ __forceinline__ float tanh_(float x) {
    x = fminf(fmaxf(x, -15.0f), 15.0f);
    float e = __expf(-2.0f * x);
    return __fdividef(1.0f - e, 1.0f + e);
}

__global__ void reset_kernel() {
    g_flags[threadIdx.x] = 0;
}

__global__ __launch_bounds__(256, 1) void fused_kernel(
    const float* __restrict__ x,      // [T,B,300]
    const float* __restrict__ Wih0,   // [8,300]
    const float* __restrict__ bih0,
    const float* __restrict__ bhh0,
    const float* __restrict__ h0in,   // [2,B,2]
    const float* __restrict__ c0in,
    const float* __restrict__ Whh0,   // [8,2]
    const float* __restrict__ Wih1,   // [8,2]
    const float* __restrict__ Whh1,   // [8,2]
    const float* __restrict__ bih1,
    const float* __restrict__ bhh1,
    const float* __restrict__ Wlin,   // [1,2]
    const float* __restrict__ blin,
    float* __restrict__ out,          // [B]
    int nprod)
{
    extern __shared__ float smem[];
    const int bid = blockIdx.x;
    const int tid = threadIdx.x;

    if (bid < nprod) {
        // =================== PRODUCER ===================
        float* sW = smem;                  // sW[d*8+g] = Wih0[g*300+d]
        float* sB = smem + SW_FLOATS;
        float4* sbuf4 = reinterpret_cast<float4*>(smem + SX_OFF);

        for (int i = tid; i < DD * H4; i += 256) {
            int d = i >> 3, g = i & 7;
            sW[i] = Wih0[g * DD + d];
        }
        if (tid < H4) sB[tid] = bih0[tid] + bhh0[tid];
        __syncthreads();

        if (bid >= TT) return;   // no task (can't happen with nprod<=256)

        ulonglong2 bias01 = *reinterpret_cast<const ulonglong2*>(&sB[0]);
        ulonglong2 bias23 = *reinterpret_cast<const ulonglong2*>(&sB[4]);
        const ulonglong2* wpb = reinterpret_cast<const ulonglong2*>(sW);
        const float4* x4 = reinterpret_cast<const float4*>(x);

        // staging geometry: op i = j*250 + tid  ->  row r = j*50 + tid/5, q = tid%5
        const int tr = tid / 5;
        const int tq = tid - tr * 5;
        const int goff = tr * 75 + tq;   // global float4 offset within (t,c) base
        const int soff = tr * 5  + tq;   // smem  float4 offset stride-group

        float4 st[NSTG];

        // prologue: load chunk (bid, 0) into registers
        if (tid < 250) {
            const float4* base = x4 + (size_t)bid * (BB * (DD / 4));
            #pragma unroll
            for (int j = 0; j < NSTG; j++)
                st[j] = base[j * 3750 + goff];
        }

        #pragma unroll 1
        for (int t = bid; t < TT; t += nprod) {
            unsigned long long acc[4][4];
            #pragma unroll
            for (int k = 0; k < 4; k++) {
                acc[k][0] = bias01.x; acc[k][1] = bias01.y;
                acc[k][2] = bias23.x; acc[k][3] = bias23.y;
            }

            #pragma unroll 1
            for (int c = 0; c < NCH; c++) {
                // ---- commit registers -> smem buffer ----
                if (tid < 250) {
                    #pragma unroll
                    for (int j = 0; j < NSTG; j++)
                        sbuf4[j * 250 + soff] = st[j];
                }
                __syncthreads();

                // ---- issue next chunk's LDG batch (covered by compute below) ----
                {
                    int nt = t, nc = c + 1;
                    if (nc == NCH) { nt = t + nprod; nc = 0; }
                    if (nt < TT && tid < 250) {
                        const float4* base = x4 + (size_t)nt * (BB * (DD / 4)) + nc * 5;
                        #pragma unroll
                        for (int j = 0; j < NSTG; j++)
                            st[j] = base[j * 3750 + goff];
                    }
                }

                // ---- compute chunk c from smem (4 rows / thread) ----
                if (tid < 250) {
                    const float* sx = smem + SX_OFF;
                    const float4* xr0 = reinterpret_cast<const float4*>(sx + (tid      ) * DCH);
                    const float4* xr1 = reinterpret_cast<const float4*>(sx + (tid + 250) * DCH);
                    const float4* xr2 = reinterpret_cast<const float4*>(sx + (tid + 500) * DCH);
                    const float4* xr3 = reinterpret_cast<const float4*>(sx + (tid + 750) * DCH);
                    const ulonglong2* wp = wpb + c * (DCH * 2);
                    #pragma unroll
                    for (int dq = 0; dq < DCH / 4; dq++) {
                        float4 xv[4];
                        xv[0] = xr0[dq]; xv[1] = xr1[dq];
                        xv[2] = xr2[dq]; xv[3] = xr3[dq];
                        #pragma unroll
                        for (int j = 0; j < 4; j++) {
                            ulonglong2 wA = wp[(dq * 4 + j) * 2];
                            ulonglong2 wB = wp[(dq * 4 + j) * 2 + 1];
                            const float xs0 = (j == 0) ? xv[0].x : (j == 1) ? xv[0].y : (j == 2) ? xv[0].z : xv[0].w;
                            const float xs1 = (j == 0) ? xv[1].x : (j == 1) ? xv[1].y : (j == 2) ? xv[1].z : xv[1].w;
                            const float xs2 = (j == 0) ? xv[2].x : (j == 1) ? xv[2].y : (j == 2) ? xv[2].z : xv[2].w;
                            const float xs3 = (j == 0) ? xv[3].x : (j == 1) ? xv[3].y : (j == 2) ? xv[3].z : xv[3].w;
                            unsigned long long p0 = pack2(xs0), p1 = pack2(xs1);
                            unsigned long long p2 = pack2(xs2), p3 = pack2(xs3);
                            fma2(acc[0][0], p0, wA.x); fma2(acc[0][1], p0, wA.y);
                            fma2(acc[0][2], p0, wB.x); fma2(acc[0][3], p0, wB.y);
                            fma2(acc[1][0], p1, wA.x); fma2(acc[1][1], p1, wA.y);
                            fma2(acc[1][2], p1, wB.x); fma2(acc[1][3], p1, wB.y);
                            fma2(acc[2][0], p2, wA.x); fma2(acc[2][1], p2, wA.y);
                            fma2(acc[2][2], p2, wB.x); fma2(acc[2][3], p2, wB.y);
                            fma2(acc[3][0], p3, wA.x); fma2(acc[3][1], p3, wA.y);
                            fma2(acc[3][2], p3, wB.x); fma2(acc[3][3], p3, wB.y);
                        }
                    }
                }
                __syncthreads();   // all reads done before next STS overwrites buffer
            }

            // ---- writeback + publish ----
            if (tid < 250) {
                #pragma unroll
                for (int k = 0; k < 4; k++) {
                    const int row = t * BB + tid + k * 250;
                    float4 o0, o1;
                    unpack2(acc[k][0], o0.x, o0.y);
                    unpack2(acc[k][1], o0.z, o0.w);
                    unpack2(acc[k][2], o1.x, o1.y);
                    unpack2(acc[k][3], o1.z, o1.w);
                    float4* dst = reinterpret_cast<float4*>(&g_xg[(size_t)row * H4]);
                    dst[0] = o0;
                    dst[1] = o1;
                }
            }
            __threadfence();
            __syncthreads();
            if (tid == 0) set_flag(t);
        }
        return;
    }

    // =================== CONSUMER ===================
    // 16 blocks x 4 warps (threads 0..127). Lanes 0-15: layer0 of 16 elements,
    // lanes 16-31: layer1 of the same elements, lagged one timestep.
    if (tid >= 128) return;
    const int warp = tid >> 5;
    const int lane = tid & 31;
    const bool l1  = (lane >= 16);
    const int e    = ((bid - nprod) * 4 + warp) * 16 + (lane & 15);
    const int b    = (e < BB) ? e : (BB - 1);

    float A0[H4], A1[H4], C0[H4], C1[H4], vb[H4];
    float ha, hb, ca, cb;
    float hpa = 0.0f, hpb = 0.0f;

    if (!l1) {
        #pragma unroll
        for (int g = 0; g < H4; g++) {
            A0[g] = __ldg(&Whh0[g * 2 + 0]);
            A1[g] = __ldg(&Whh0[g * 2 + 1]);
            C0[g] = 0.0f; C1[g] = 0.0f; vb[g] = 0.0f;
        }
        ha = h0in[b * 2 + 0]; hb = h0in[b * 2 + 1];
        ca = c0in[b * 2 + 0]; cb = c0in[b * 2 + 1];
    } else {
        #pragma unroll
        for (int g = 0; g < H4; g++) {
            A0[g] = __ldg(&Whh1[g * 2 + 0]);
            A1[g] = __ldg(&Whh1[g * 2 + 1]);
            C0[g] = __ldg(&Wih1[g * 2 + 0]);
            C1[g] = __ldg(&Wih1[g * 2 + 1]);
            vb[g] = __ldg(&bih1[g]) + __ldg(&bhh1[g]);
        }
        ha = h0in[BB * 2 + b * 2 + 0]; hb = h0in[BB * 2 + b * 2 + 1];
        ca = c0in[BB * 2 + b * 2 + 0]; cb = c0in[BB * 2 + b * 2 + 1];
    }
    const float wl0 = __ldg(&Wlin[0]), wl1 = __ldg(&Wlin[1]), bl = __ldg(&blin[0]);

    const float4* xg4 = reinterpret_cast<const float4*>(g_xg);
    const int idx0 = b * 2;

    wait_flag(0);
    if (!l1) {
        float4 v0 = xg4[idx0];
        float4 v1 = xg4[idx0 + 1];
        vb[0] = v0.x; vb[1] = v0.y; vb[2] = v0.z; vb[3] = v0.w;
        vb[4] = v1.x; vb[5] = v1.y; vb[6] = v1.z; vb[7] = v1.w;
    }

    for (int s = 0; s <= TT; s++) {
        float4 n0, n1;
        const bool pf = (s + 1 < TT);
        if (pf) {
            wait_flag(s + 1);
            if (!l1) {
                n0 = xg4[idx0 + (s + 1) * (BB * 2)];
                n1 = xg4[idx0 + (s + 1) * (BB * 2) + 1];
            }
        }

        float pre[H4];
        #pragma unroll
        for (int g = 0; g < H4; g++)
            pre[g] = fmaf(C0[g], hpa, fmaf(C1[g], hpb, vb[g]));
        #pragma unroll
        for (int g = 0; g < H4; g++)
            pre[g] = fmaf(A0[g], ha, fmaf(A1[g], hb, pre[g]));

        float i0 = sigf(pre[0]),  i1 = sigf(pre[1]);
        float f0 = sigf(pre[2]),  f1 = sigf(pre[3]);
        float g0 = tanh_(pre[4]), g1 = tanh_(pre[5]);
        float o0 = sigf(pre[6]),  o1 = sigf(pre[7]);
        float nca = fmaf(f0, ca, i0 * g0);
        float ncb = fmaf(f1, cb, i1 * g1);
        float nha = o0 * tanh_(nca);
        float nhb = o1 * tanh_(ncb);

        const bool valid = l1 ? (s >= 1) : (s < TT);
        if (valid) { ca = nca; cb = ncb; ha = nha; hb = nhb; }

        hpa = __shfl_up_sync(0xffffffffu, ha, 16);
        hpb = __shfl_up_sync(0xffffffffu, hb, 16);

        if (pf && !l1) {
            vb[0] = n0.x; vb[1] = n0.y; vb[2] = n0.z; vb[3] = n0.w;
            vb[4] = n1.x; vb[5] = n1.y; vb[6] = n1.z; vb[7] = n1.w;
        }
    }

    if (l1 && e < BB)
        out[b] = fmaf(wl0, ha, fmaf(wl1, hb, bl));
}

// ---------------------------------------------------------------------------
extern "C" void kernel_launch(void* const* d_in, const int* in_sizes, int n_in,
                              void* d_out, int out_size)
{
    const float* x     = (const float*)d_in[0];
    const float* h0    = (const float*)d_in[1];
    const float* c0    = (const float*)d_in[2];
    const float* Wih0  = (const float*)d_in[3];
    const float* Whh0  = (const float*)d_in[4];
    const float* bih0  = (const float*)d_in[5];
    const float* bhh0  = (const float*)d_in[6];
    const float* Wih1  = (const float*)d_in[7];
    const float* Whh1  = (const float*)d_in[8];
    const float* bih1  = (const float*)d_in[9];
    const float* bhh1  = (const float*)d_in[10];
    const float* Wlin  = (const float*)d_in[11];
    const float* blin  = (const float*)d_in[12];
    float* out = (float*)d_out;

    int dev = 0, nsm = 148;
    cudaGetDevice(&dev);
    cudaDeviceGetAttribute(&nsm, cudaDevAttrMultiProcessorCount, dev);
    if (nsm < NCONS_BLK + 8) nsm = NCONS_BLK + 8;
    int nprod = nsm - NCONS_BLK;
    if (nprod > TT) nprod = TT;   // at most one producer block per timestep

    cudaFuncSetAttribute(fused_kernel, cudaFuncAttributeMaxDynamicSharedMemorySize, SMEM_BYTES);

    reset_kernel<<<1, TT>>>();
    fused_kernel<<<nprod + NCONS_BLK, 256, SMEM_BYTES>>>(
        x, Wih0, bih0, bhh0,
        h0, c0, Whh0, Wih1, Whh1, bih1, bhh1, Wlin, blin,
        out, nprod);
}